// round 5
// baseline (speedup 1.0000x reference)
#include <cuda_runtime.h>
#include <cuda_bf16.h>
#include <math.h>
#include <stdint.h>

#define HW_   4096
#define NPIX_ 16384

// tcgen05 exists only in the arch-specific (sm_103a/sm_100a) pass.
#if defined(__CUDA_ARCH__) && (defined(__CUDA_ARCH_FEAT_SM103_ALL) || defined(__CUDA_ARCH_FEAT_SM100_ALL))
#define HAS_TC 1
#else
#define HAS_TC 0
#endif

// ---------------------------------------------------------------------------
// Scratch (device globals; allocation is forbidden)
// ---------------------------------------------------------------------------
__device__ float g_featsA[4 * 512 * 4096];
__device__ float g_featsB[4 * 512 * 4096];
__device__ float g_v[4 * 512 * 4096];
__device__ float g_qk[4 * 128 * 4096];
__device__ float g_attn[4 * 4096 * 128];
__device__ float g_bqk[128];
__device__ __nv_bfloat16 g_xhi[4 * 4096 * 2048];
__device__ __nv_bfloat16 g_xlo[4 * 4096 * 2048];
__device__ __nv_bfloat16 g_fhi[4 * 4096 * 512];
__device__ __nv_bfloat16 g_flo[4 * 4096 * 512];
__device__ __nv_bfloat16 g_w1hi[9 * 512 * 2048];
__device__ __nv_bfloat16 g_w1lo[9 * 512 * 2048];
__device__ __nv_bfloat16 g_w2hi[9 * 512 * 512];
__device__ __nv_bfloat16 g_w2lo[9 * 512 * 512];
__device__ __nv_bfloat16 g_wqkhi[128 * 512];
__device__ __nv_bfloat16 g_wqklo[128 * 512];
__device__ __nv_bfloat16 g_wvhi[512 * 512];
__device__ __nv_bfloat16 g_wvlo[512 * 512];

// ---------------------------------------------------------------------------
// Generic helpers (valid on base sm_103)
// ---------------------------------------------------------------------------
__device__ __forceinline__ unsigned smem_u32(const void* p) {
    unsigned a;
    asm("{ .reg .u64 t; cvta.to.shared.u64 t, %1; cvt.u32.u64 %0, t; }"
        : "=r"(a) : "l"(p));
    return a;
}
__device__ __forceinline__ unsigned elect_one() {
    unsigned p;
    asm volatile("{ .reg .pred p; elect.sync _|p, 0xFFFFFFFF; selp.b32 %0, 1, 0, p; }"
                 : "=r"(p));
    return p;
}
#define SW128(o) ((o) ^ (((o) >> 3) & 0x70))
__device__ __forceinline__ void mbar_init(unsigned mbar, unsigned cnt) {
    asm volatile("mbarrier.init.shared.b64 [%0], %1;" :: "r"(mbar), "r"(cnt) : "memory");
}
__device__ __forceinline__ void mbar_wait(unsigned mbar, unsigned phase) {
    asm volatile(
        "{\n\t.reg .pred P;\n\t"
        "WL_%=:\n\t"
        "mbarrier.try_wait.parity.acquire.cta.shared::cta.b64 P, [%0], %1, 0x989680;\n\t"
        "@P bra.uni WD_%=;\n\t"
        "bra.uni WL_%=;\n\t"
        "WD_%=:\n\t}"
        :: "r"(mbar), "r"(phase) : "memory");
}
__device__ __forceinline__ void fence_async_shared() {
    asm volatile("fence.proxy.async;" ::: "memory");
}

// ---------------------------------------------------------------------------
// tcgen05 / cluster helpers (arch-specific pass only)
// ---------------------------------------------------------------------------
#if HAS_TC
static constexpr unsigned long long SMEM_DESC_BASE_SW128 =
    (2ull << 61) | (1ull << 46) | (64ull << 32) | (1ull << 16);
__device__ __forceinline__ unsigned long long make_desc(unsigned addr) {
    return SMEM_DESC_BASE_SW128 | ((unsigned long long)(addr >> 4) & 0x3FFFull);
}
__device__ __forceinline__ void mbar_wait_cluster(unsigned mbar, unsigned phase) {
    asm volatile(
        "{\n\t.reg .pred P;\n\t"
        "WL_%=:\n\t"
        "mbarrier.try_wait.parity.acquire.cluster.shared::cta.b64 P, [%0], %1, 0x989680;\n\t"
        "@P bra.uni WD_%=;\n\t"
        "bra.uni WL_%=;\n\t"
        "WD_%=:\n\t}"
        :: "r"(mbar), "r"(phase) : "memory");
}
__device__ __forceinline__ void mbar_arrive_rank0(unsigned local_addr) {
    asm volatile(
        "{\n\t.reg .b32 r;\n\t"
        "mapa.shared::cluster.u32 r, %0, 0;\n\t"
        "mbarrier.arrive.shared::cluster.b64 _, [r];\n\t}"
        :: "r"(local_addr) : "memory");
}
__device__ __forceinline__ void cluster_sync_() {
    asm volatile("barrier.cluster.arrive.aligned;" ::: "memory");
    asm volatile("barrier.cluster.wait.aligned;" ::: "memory");
}
__device__ __forceinline__ void tmem_alloc_cg1(unsigned dst_smem, unsigned ncols) {
    asm volatile("tcgen05.alloc.cta_group::1.sync.aligned.shared::cta.b32 [%0], %1;"
                 :: "r"(dst_smem), "r"(ncols) : "memory");
}
__device__ __forceinline__ void tmem_dealloc_cg1(unsigned tmem, unsigned ncols) {
    asm volatile("tcgen05.dealloc.cta_group::1.sync.aligned.b32 %0, %1;"
                 :: "r"(tmem), "r"(ncols));
}
__device__ __forceinline__ void tmem_alloc_cg2(unsigned dst_smem, unsigned ncols) {
    asm volatile("tcgen05.alloc.cta_group::2.sync.aligned.shared::cta.b32 [%0], %1;"
                 :: "r"(dst_smem), "r"(ncols) : "memory");
}
__device__ __forceinline__ void tmem_dealloc_cg2(unsigned tmem, unsigned ncols) {
    asm volatile("tcgen05.dealloc.cta_group::2.sync.aligned.b32 %0, %1;"
                 :: "r"(tmem), "r"(ncols));
}
__device__ __forceinline__ void tc_relinquish_cg2() {
    asm volatile("tcgen05.relinquish_alloc_permit.cta_group::2.sync.aligned;");
}
__device__ __forceinline__ void tc_commit_cg1(unsigned mbar) {
    asm volatile("tcgen05.commit.cta_group::1.mbarrier::arrive::one.shared::cluster.b64 [%0];"
                 :: "r"(mbar) : "memory");
}
__device__ __forceinline__ void tc_commit_mc_cg2(unsigned mbar, unsigned short mask) {
    asm volatile("tcgen05.commit.cta_group::2.mbarrier::arrive::one.shared::cluster.multicast::cluster.b64 [%0], %1;"
                 :: "r"(mbar), "h"(mask) : "memory");
}
__device__ __forceinline__ void tc_fence_after() {
    asm volatile("tcgen05.fence::after_thread_sync;" ::: "memory");
}
__device__ __forceinline__ void tc_wait_ld() {
    asm volatile("tcgen05.wait::ld.sync.aligned;" ::: "memory");
}
__device__ __forceinline__ void mma_cg1(unsigned d, unsigned long long ad,
                                        unsigned long long bd, unsigned idesc, unsigned en) {
    asm volatile(
        "{\n\t.reg .pred p;\n\tsetp.ne.u32 p, %4, 0;\n\t"
        "tcgen05.mma.cta_group::1.kind::f16 [%0], %1, %2, %3, {%5, %5, %5, %5}, p;\n\t}"
        :: "r"(d), "l"(ad), "l"(bd), "r"(idesc), "r"(en), "r"(0u) : "memory");
}
__device__ __forceinline__ void mma_cg2(unsigned d, unsigned long long ad,
                                        unsigned long long bd, unsigned idesc, unsigned en) {
    asm volatile(
        "{\n\t.reg .pred p;\n\tsetp.ne.u32 p, %4, 0;\n\t"
        "tcgen05.mma.cta_group::2.kind::f16 [%0], %1, %2, %3, "
        "{%5, %5, %5, %5, %5, %5, %5, %5}, p;\n\t}"
        :: "r"(d), "l"(ad), "l"(bd), "r"(idesc), "r"(en), "r"(0u) : "memory");
}
__device__ __forceinline__ void tmem_ld32(unsigned* r, unsigned addr) {
    asm volatile(
        "tcgen05.ld.sync.aligned.32x32b.x32.b32 "
        "{%0, %1, %2, %3, %4, %5, %6, %7, "
        " %8, %9, %10, %11, %12, %13, %14, %15, "
        " %16, %17, %18, %19, %20, %21, %22, %23, "
        " %24, %25, %26, %27, %28, %29, %30, %31}, [%32];"
        : "=r"(r[0]),  "=r"(r[1]),  "=r"(r[2]),  "=r"(r[3]),
          "=r"(r[4]),  "=r"(r[5]),  "=r"(r[6]),  "=r"(r[7]),
          "=r"(r[8]),  "=r"(r[9]),  "=r"(r[10]), "=r"(r[11]),
          "=r"(r[12]), "=r"(r[13]), "=r"(r[14]), "=r"(r[15]),
          "=r"(r[16]), "=r"(r[17]), "=r"(r[18]), "=r"(r[19]),
          "=r"(r[20]), "=r"(r[21]), "=r"(r[22]), "=r"(r[23]),
          "=r"(r[24]), "=r"(r[25]), "=r"(r[26]), "=r"(r[27]),
          "=r"(r[28]), "=r"(r[29]), "=r"(r[30]), "=r"(r[31])
        : "r"(addr));
}
__device__ __forceinline__ void cp16(unsigned dst, const void* src, unsigned bytes) {
    asm volatile("cp.async.cg.shared.global [%0], [%1], 16, %2;"
                 :: "r"(dst), "l"(src), "r"(bytes) : "memory");
}
__device__ __forceinline__ void cp_commit_wait0() {
    asm volatile("cp.async.commit_group;" ::: "memory");
    asm volatile("cp.async.wait_group 0;" ::: "memory");
}
#endif

// ---------------------------------------------------------------------------
// Prep kernels: fp32 -> bf16 hi/lo decomposition (+ layout transforms)
// ---------------------------------------------------------------------------
__device__ __forceinline__ void split_bf16(float x, __nv_bfloat16& h, __nv_bfloat16& l) {
    h = __float2bfloat16(x);
    l = __float2bfloat16(x - __bfloat162float(h));
}

// NCHW fp32 -> NHWC bf16 hi/lo (only needed for the conv1 input x)
__global__ void prep_act(const float* __restrict__ src,
                         __nv_bfloat16* __restrict__ dhi,
                         __nv_bfloat16* __restrict__ dlo, int CIN) {
    __shared__ float t[32][33];
    const int b = blockIdx.z, ct = blockIdx.y * 32, pt = blockIdx.x * 32;
    const int tx = threadIdx.x, ty = threadIdx.y;
    for (int i = ty; i < 32; i += 8)
        t[i][tx] = src[((size_t)(b * CIN + ct + i)) * HW_ + pt + tx];
    __syncthreads();
    for (int i = ty; i < 32; i += 8) {
        float x = t[tx][i];
        __nv_bfloat16 h, l;
        split_bf16(x, h, l);
        size_t o = ((size_t)(b * HW_ + pt + i)) * CIN + ct + tx;
        dhi[o] = h;
        dlo[o] = l;
    }
}

__global__ void prep_wconv(const float* __restrict__ W,
                           __nv_bfloat16* __restrict__ dhi,
                           __nv_bfloat16* __restrict__ dlo, int M, int CIN) {
    int idx = blockIdx.x * 256 + threadIdx.x;
    if (idx >= M * CIN) return;
#pragma unroll
    for (int tap = 0; tap < 9; tap++) {
        float x = W[(size_t)idx * 9 + tap];
        __nv_bfloat16 h, l;
        split_bf16(x, h, l);
        size_t o = (size_t)tap * M * CIN + idx;
        dhi[o] = h;
        dlo[o] = l;
    }
}

__global__ void prep_wlin(const float* __restrict__ W,
                          __nv_bfloat16* __restrict__ dhi,
                          __nv_bfloat16* __restrict__ dlo, int n) {
    int i = blockIdx.x * 256 + threadIdx.x;
    if (i >= n) return;
    __nv_bfloat16 h, l;
    split_bf16(W[i], h, l);
    dhi[i] = h;
    dlo[i] = l;
}

// q/k weight stack (M=128) + stacked bias, one launch
__global__ void prep_wqk(const float* __restrict__ qw, const float* __restrict__ kw,
                         const float* __restrict__ qb, const float* __restrict__ kb,
                         __nv_bfloat16* __restrict__ dhi, __nv_bfloat16* __restrict__ dlo,
                         float* __restrict__ bias) {
    int i = blockIdx.x * 256 + threadIdx.x;
    if (i < 128) bias[i] = (i < 64) ? qb[i] : kb[i - 64];
    if (i >= 128 * 512) return;
    float x = (i < 64 * 512) ? qw[i] : kw[i - 64 * 512];
    __nv_bfloat16 h, l;
    split_bf16(x, h, l);
    dhi[i] = h;
    dlo[i] = l;
}

// ---------------------------------------------------------------------------
// cg2 implicit-conv GEMM: cluster of 2 CTAs, M=256 per cluster (128 per CTA),
// 4 n-tiles of 128 pixels (512 pixels per cluster), bf16-split 3-MMA chains.
// WB=1: epilogue additionally writes bf16 hi/lo NHWC (feeds next GEMM stage).
// ---------------------------------------------------------------------------
template<int CIN, int TAPS, int EPI, int WB>
__global__ void __launch_bounds__(256, 1) __cluster_dims__(2, 1, 1)
mma_conv_cg2(const __nv_bfloat16* __restrict__ Whi, const __nv_bfloat16* __restrict__ Wlo,
             const __nv_bfloat16* __restrict__ Xhi, const __nv_bfloat16* __restrict__ Xlo,
             const float* __restrict__ e0, const float* __restrict__ e1,
             const float* __restrict__ e2, const float* __restrict__ e3,
             float* __restrict__ Y,
             __nv_bfloat16* __restrict__ Dhi, __nv_bfloat16* __restrict__ Dlo,
             int Mtot)
{
#if HAS_TC
    constexpr int NCHUNK = TAPS * (CIN / 64);
    constexpr int A_HI = 0;            // 128 rows x 128B
    constexpr int A_LO = 16384;
    constexpr int B_HI0 = 32768;       // 4 tiles x 64 rows x 128B
    constexpr int B_LO0 = 65536;
    constexpr int STAGE = 98304;       // 96 KB
    constexpr unsigned IDESC2 =
        (1u << 4) | (1u << 7) | (1u << 10) | (16u << 17) | (16u << 24);

    extern __shared__ char dyn_smem[];
    __shared__ __align__(8) unsigned long long s_full[2];
    __shared__ __align__(8) unsigned long long s_done[2];
    __shared__ unsigned s_tmem[1];

    char* sm = (char*)((((uintptr_t)dyn_smem) + 1023) & ~(uintptr_t)1023);
    const unsigned sbase = smem_u32(sm);

    const int tid  = threadIdx.x;
    const int wid  = tid >> 5;
    const int lane = tid & 31;
    const unsigned rank = blockIdx.x & 1;
    const int m_base = (blockIdx.x >> 1) * 256;
    const int n_base = blockIdx.y * 512;
    const int bb   = n_base >> 12;
    const int sp00 = n_base & 4095;

    if (wid == 0) tmem_alloc_cg2(smem_u32(&s_tmem[0]), 512);
    if (tid == 0) {
        mbar_init(smem_u32(&s_full[0]), 2);
        mbar_init(smem_u32(&s_full[1]), 2);
        mbar_init(smem_u32(&s_done[0]), 1);
        mbar_init(smem_u32(&s_done[1]), 1);
    }
    __syncthreads();
    unsigned tmem;
    asm volatile("ld.shared.b32 %0, [%1];" : "=r"(tmem) : "r"(smem_u32(&s_tmem[0])));
    const unsigned fullb[2] = { smem_u32(&s_full[0]), smem_u32(&s_full[1]) };
    const unsigned doneb[2] = { smem_u32(&s_done[0]), smem_u32(&s_done[1]) };
    cluster_sync_();

    int dph[2] = {0, 0};
    int fph[2] = {0, 0};

    for (int chunk = 0; chunk < NCHUNK; ++chunk) {
        const int s   = chunk & 1;
        const int tap = (TAPS == 1) ? 0 : chunk / (CIN / 64);
        const int cb  = (TAPS == 1) ? chunk * 64 : (chunk % (CIN / 64)) * 64;
        const int dh  = (TAPS == 9) ? (tap / 3 - 1) : 0;
        const int dw  = (TAPS == 9) ? (tap % 3 - 1) : 0;

        if (chunk >= 2) { mbar_wait(doneb[s], dph[s]); dph[s] ^= 1; }

        const unsigned stg = sbase + s * STAGE;

        {   // A: this CTA's 128 M-rows x 64 ch (hi+lo)
            const __nv_bfloat16* srcH =
                Whi + ((size_t)tap * Mtot + m_base + rank * 128) * CIN + cb;
            const __nv_bfloat16* srcL =
                Wlo + ((size_t)tap * Mtot + m_base + rank * 128) * CIN + cb;
#pragma unroll
            for (int u = 0; u < 4; ++u) {
                int l = u * 256 + tid;
                int row = l >> 3, c16 = l & 7;
                size_t go = (size_t)row * CIN + c16 * 8;
                unsigned so = SW128((unsigned)(row * 128 + c16 * 16));
                cp16(stg + A_HI + so, srcH + go, 16);
                cp16(stg + A_LO + so, srcL + go, 16);
            }
        }
        {   // B: 4 n-tiles, this CTA's 64-row half of each, tap-shifted, zfill OOB
#pragma unroll
            for (int u = 0; u < 8; ++u) {
                int l = u * 256 + tid;
                int t = l >> 9, r = (l >> 3) & 63, c16 = l & 7;
                int sp = sp00 + t * 128 + (int)rank * 64 + r;
                int h = (sp >> 6) + dh, w = (sp & 63) + dw;
                bool ok = ((unsigned)h < 64u) && ((unsigned)w < 64u);
                unsigned bytes = ok ? 16u : 0u;
                size_t go = ((size_t)(bb * HW_ + (ok ? h * 64 + w : 0))) * CIN + cb + c16 * 8;
                unsigned so = SW128((unsigned)(r * 128 + c16 * 16));
                cp16(stg + B_HI0 + t * 8192 + so, Xhi + go, bytes);
                cp16(stg + B_LO0 + t * 8192 + so, Xlo + go, bytes);
            }
        }
        cp_commit_wait0();
        __syncthreads();
        if (tid == 0) {
            fence_async_shared();
            mbar_arrive_rank0(fullb[s]);
        }
        if (rank == 0 && wid == 0 && elect_one()) {
            mbar_wait_cluster(fullb[s], fph[s]); fph[s] ^= 1;
            unsigned long long dAh = make_desc(stg + A_HI);
            unsigned long long dAl = make_desc(stg + A_LO);
#pragma unroll
            for (int t = 0; t < 4; ++t) {
                unsigned d = tmem + t * 128;
                unsigned long long dBh = make_desc(stg + B_HI0 + t * 8192);
                unsigned long long dBl = make_desc(stg + B_LO0 + t * 8192);
#pragma unroll
                for (int kk = 0; kk < 4; ++kk) {
                    unsigned en0 = (chunk > 0 || kk > 0) ? 1u : 0u;
                    mma_cg2(d, dAh + kk * 2, dBh + kk * 2, IDESC2, en0);
                    mma_cg2(d, dAh + kk * 2, dBl + kk * 2, IDESC2, 1u);
                    mma_cg2(d, dAl + kk * 2, dBh + kk * 2, IDESC2, 1u);
                }
            }
            tc_commit_mc_cg2(doneb[s], 0x3);
        }
    }

    {
        int s0 = (NCHUNK - 2) & 1, s1 = (NCHUNK - 1) & 1;
        mbar_wait(doneb[s0], dph[s0]); dph[s0] ^= 1;
        mbar_wait(doneb[s1], dph[s1]); dph[s1] ^= 1;
    }
    tc_fence_after();

    // --- epilogue ---
    {
        const int wg = wid >> 2;
        const int mg = m_base + (int)rank * 128 + (wid & 3) * 32 + lane;
        float sc, sh;
        if (EPI == 1) {
            float tt = e0[mg] * rsqrtf(e3[mg] + 1e-5f);
            sc = tt;
            sh = e1[mg] - e2[mg] * tt;
        } else {
            sc = 1.f;
            sh = e0[mg];
        }
        float* yrow = Y + ((size_t)(bb * Mtot + mg)) * HW_ + sp00;
#pragma unroll
        for (int ti = 0; ti < 2; ++ti) {
            int t = wg * 2 + ti;
#pragma unroll
            for (int cb4 = 0; cb4 < 4; ++cb4) {
                unsigned r[32];
                tmem_ld32(r, tmem + t * 128 + cb4 * 32);
                tc_wait_ld();
#pragma unroll
                for (int j = 0; j < 32; j += 4) {
                    float4 v;
                    v.x = fmaf(__uint_as_float(r[j + 0]), sc, sh);
                    v.y = fmaf(__uint_as_float(r[j + 1]), sc, sh);
                    v.z = fmaf(__uint_as_float(r[j + 2]), sc, sh);
                    v.w = fmaf(__uint_as_float(r[j + 3]), sc, sh);
                    if (EPI == 1) {
                        v.x = fmaxf(v.x, 0.f); v.y = fmaxf(v.y, 0.f);
                        v.z = fmaxf(v.z, 0.f); v.w = fmaxf(v.w, 0.f);
                    }
                    *(float4*)(yrow + t * 128 + cb4 * 32 + j) = v;
                    if (WB) {
                        size_t ob = ((size_t)bb * HW_ + sp00 + t * 128 + cb4 * 32 + j) * 512 + mg;
                        __nv_bfloat16 hh, ll;
                        split_bf16(v.x, hh, ll); Dhi[ob]           = hh; Dlo[ob]           = ll;
                        split_bf16(v.y, hh, ll); Dhi[ob + 512]     = hh; Dlo[ob + 512]     = ll;
                        split_bf16(v.z, hh, ll); Dhi[ob + 1024]    = hh; Dlo[ob + 1024]    = ll;
                        split_bf16(v.w, hh, ll); Dhi[ob + 1536]    = hh; Dlo[ob + 1536]    = ll;
                    }
                }
            }
        }
    }
    __syncthreads();
    if (wid == 0) {
        tc_relinquish_cg2();
        tmem_dealloc_cg2(tmem, 512);
    }
    cluster_sync_();
#endif
}

// ---------------------------------------------------------------------------
// cg1 GEMM for the small q/k projection (M=128)
// ---------------------------------------------------------------------------
template<int CIN, int EPI>
__global__ void __launch_bounds__(256, 1)
mma_proj_cg1(const __nv_bfloat16* __restrict__ Whi, const __nv_bfloat16* __restrict__ Wlo,
             const __nv_bfloat16* __restrict__ Xhi, const __nv_bfloat16* __restrict__ Xlo,
             const float* __restrict__ e0, float* __restrict__ Y, int Mtot)
{
#if HAS_TC
    constexpr int A_BYTES = 128 * 128;
    constexpr int B_BYTES = 128 * 128;
    constexpr int STAGE   = 2 * A_BYTES + 2 * B_BYTES;
    constexpr int NCHUNK  = CIN / 64;
    constexpr unsigned IDESC =
        (1u << 4) | (1u << 7) | (1u << 10) | (16u << 17) | (8u << 24);

    extern __shared__ char dyn_smem[];
    __shared__ __align__(8) unsigned long long s_mbar[2];
    __shared__ unsigned s_tmem[1];

    char* sm = (char*)((((uintptr_t)dyn_smem) + 1023) & ~(uintptr_t)1023);
    const unsigned sbase = smem_u32(sm);
    const int tid = threadIdx.x;
    const int wid = tid >> 5;
    const int lane = tid & 31;

    if (wid == 0) tmem_alloc_cg1(smem_u32(&s_tmem[0]), 256);
    if (tid == 0) { mbar_init(smem_u32(&s_mbar[0]), 1); mbar_init(smem_u32(&s_mbar[1]), 1); }
    __syncthreads();
    unsigned tmem;
    asm volatile("ld.shared.b32 %0, [%1];" : "=r"(tmem) : "r"(smem_u32(&s_tmem[0])));
    const unsigned mbar[2] = { smem_u32(&s_mbar[0]), smem_u32(&s_mbar[1]) };

    const int n_base = blockIdx.y * 128;
    const int bb  = n_base >> 12;
    const int sp0 = n_base & 4095;
    int ph[2] = {0, 0};

    for (int chunk = 0; chunk < NCHUNK; ++chunk) {
        const int s  = chunk & 1;
        const int cb = chunk * 64;
        if (chunk >= 2) { mbar_wait(mbar[s], ph[s]); ph[s] ^= 1; }

        char* aHi = sm + s * STAGE;
        char* aLo = aHi + A_BYTES;
        char* bHi = aLo + A_BYTES;
        char* bLo = bHi + B_BYTES;
#pragma unroll
        for (int u = 0; u < 4; ++u) {
            int l = u * 256 + tid;
            int row = l >> 3, c16 = l & 7;
            size_t go = (size_t)row * CIN + cb + c16 * 8;
            unsigned so = SW128((unsigned)(row * 128 + c16 * 16));
            *(uint4*)(aHi + so) = *(const uint4*)(Whi + go);
            *(uint4*)(aLo + so) = *(const uint4*)(Wlo + go);
        }
#pragma unroll
        for (int u = 0; u < 4; ++u) {
            int l = u * 256 + tid;
            int row = l >> 3, c16 = l & 7;
            size_t go = ((size_t)(bb * HW_ + sp0 + row)) * CIN + cb + c16 * 8;
            unsigned so = SW128((unsigned)(row * 128 + c16 * 16));
            *(uint4*)(bHi + so) = *(const uint4*)(Xhi + go);
            *(uint4*)(bLo + so) = *(const uint4*)(Xlo + go);
        }
        fence_async_shared();
        __syncthreads();

        if (wid == 0 && elect_one()) {
            unsigned long long dAh = make_desc(sbase + s * STAGE);
            unsigned long long dAl = dAh + (A_BYTES >> 4);
            unsigned long long dBh = make_desc(sbase + s * STAGE + 2 * A_BYTES);
            unsigned long long dBl = dBh + (B_BYTES >> 4);
#pragma unroll
            for (int kk = 0; kk < 4; ++kk) {
                unsigned en0 = (chunk > 0 || kk > 0) ? 1u : 0u;
                mma_cg1(tmem, dAh + kk * 2, dBh + kk * 2, IDESC, en0);
                mma_cg1(tmem, dAh + kk * 2, dBl + kk * 2, IDESC, 1u);
                mma_cg1(tmem, dAl + kk * 2, dBh + kk * 2, IDESC, 1u);
            }
            tc_commit_cg1(mbar[s]);
        }
    }
    {
        int s0 = (NCHUNK - 2) & 1, s1 = (NCHUNK - 1) & 1;
        mbar_wait(mbar[s0], ph[s0]); ph[s0] ^= 1;
        mbar_wait(mbar[s1], ph[s1]); ph[s1] ^= 1;
    }
    tc_fence_after();

    if (wid < 4) {
        const int mg = wid * 32 + lane;
        float sh = e0[mg];
        float* yrow = Y + ((size_t)(bb * Mtot + mg)) * HW_ + sp0;
#pragma unroll
        for (int cb4 = 0; cb4 < 4; ++cb4) {
            unsigned r[32];
            tmem_ld32(r, tmem + cb4 * 32);
            tc_wait_ld();
#pragma unroll
            for (int j = 0; j < 32; j += 4) {
                float4 v;
                v.x = __uint_as_float(r[j + 0]) + sh;
                v.y = __uint_as_float(r[j + 1]) + sh;
                v.z = __uint_as_float(r[j + 2]) + sh;
                v.w = __uint_as_float(r[j + 3]) + sh;
                *(float4*)(yrow + cb4 * 32 + j) = v;
            }
        }
    }
    __syncthreads();
    if (wid == 0) tmem_dealloc_cg1(tmem, 256);
#endif
}

// ---------------------------------------------------------------------------
// CCA kernels
// ---------------------------------------------------------------------------
__global__ void __launch_bounds__(256) energyH_kernel(
    const float* __restrict__ qk, float* __restrict__ attn)
{
    const int w = blockIdx.x, b = blockIdx.y;
    __shared__ float Qs[64][65];
    __shared__ float Ks[64][65];
    const int tid = threadIdx.x;
    for (int l = tid; l < 4096; l += 256) {
        int c = l >> 6, h = l & 63;
        Qs[c][h] = qk[((size_t)(b * 128 + c)) * HW_ + h * 64 + w];
        Ks[c][h] = qk[((size_t)(b * 128 + 64 + c)) * HW_ + h * 64 + w];
    }
    __syncthreads();
    const int hh = tid & 63, ig = tid >> 6;
    float acc[16];
#pragma unroll
    for (int i = 0; i < 16; i++) acc[i] = 0.f;
    for (int c = 0; c < 64; c++) {
        float qv = Qs[c][hh];
#pragma unroll
        for (int i = 0; i < 16; i++) acc[i] += qv * Ks[c][ig * 16 + i];
    }
    float* orow = attn + (size_t)(((b * 64 + hh) * 64 + w)) * 128;
#pragma unroll
    for (int i = 0; i < 16; i++) {
        int ii = ig * 16 + i;
        orow[ii] = acc[i] + ((ii == hh) ? -1000000000.0f : 0.f);
    }
}

__global__ void __launch_bounds__(256) energyW_kernel(
    const float* __restrict__ qk, float* __restrict__ attn)
{
    const int h = blockIdx.x, b = blockIdx.y;
    __shared__ float Qs[64][65];
    __shared__ float Ks[64][65];
    const int tid = threadIdx.x;
    for (int l = tid; l < 4096; l += 256) {
        int c = l >> 6, w = l & 63;
        Qs[c][w] = qk[((size_t)(b * 128 + c)) * HW_ + h * 64 + w];
        Ks[c][w] = qk[((size_t)(b * 128 + 64 + c)) * HW_ + h * 64 + w];
    }
    __syncthreads();
    const int wq = tid & 63, jg = tid >> 6;
    float acc[16];
#pragma unroll
    for (int j = 0; j < 16; j++) acc[j] = 0.f;
    for (int c = 0; c < 64; c++) {
        float qv = Qs[c][wq];
#pragma unroll
        for (int j = 0; j < 16; j++) acc[j] += qv * Ks[c][jg * 16 + j];
    }
    float* orow = attn + (size_t)(((b * 64 + h) * 64 + wq)) * 128 + 64;
#pragma unroll
    for (int j = 0; j < 16; j++) orow[jg * 16 + j] = acc[j];
}

__global__ void __launch_bounds__(256) softmax_kernel(float* __restrict__ attn)
{
    int gw = (blockIdx.x * blockDim.x + threadIdx.x) >> 5;
    if (gw >= NPIX_) return;
    int lane = threadIdx.x & 31;
    float* row = attn + (size_t)gw * 128;
    float v0 = row[lane], v1 = row[lane + 32], v2 = row[lane + 64], v3 = row[lane + 96];
    float mx = fmaxf(fmaxf(v0, v1), fmaxf(v2, v3));
#pragma unroll
    for (int o = 16; o > 0; o >>= 1) mx = fmaxf(mx, __shfl_xor_sync(0xffffffffu, mx, o));
    v0 = expf(v0 - mx); v1 = expf(v1 - mx); v2 = expf(v2 - mx); v3 = expf(v3 - mx);
    float s = v0 + v1 + v2 + v3;
#pragma unroll
    for (int o = 16; o > 0; o >>= 1) s += __shfl_xor_sync(0xffffffffu, s, o);
    float inv = 1.0f / s;
    row[lane] = v0 * inv; row[lane + 32] = v1 * inv;
    row[lane + 64] = v2 * inv; row[lane + 96] = v3 * inv;
}

__global__ void __launch_bounds__(256) aggH_kernel(
    const float* __restrict__ v, const float* __restrict__ attn,
    const float* __restrict__ fin, float* __restrict__ fout,
    const float* __restrict__ gptr)
{
    const int w = blockIdx.x, b = blockIdx.y, cbk = blockIdx.z * 64;
    __shared__ float Vs[64][65];
    __shared__ float Am[64][65];
    const int tid = threadIdx.x;
    for (int l = tid; l < 4096; l += 256) {
        int c = l >> 6, i = l & 63;
        Vs[c][i] = v[(size_t)((b * 512 + cbk + c) * 64 + i) * 64 + w];
    }
    for (int l = tid; l < 4096; l += 256) {
        int h = l >> 6, i = l & 63;
        Am[h][i] = attn[(size_t)(((b * 64 + h) * 64 + w)) * 128 + i];
    }
    __syncthreads();
    const int tc = tid & 63, hg = tid >> 6;
    float acc[16];
#pragma unroll
    for (int t = 0; t < 16; t++) acc[t] = 0.f;
    for (int i = 0; i < 64; i++) {
        float vv = Vs[tc][i];
#pragma unroll
        for (int t = 0; t < 16; t++) acc[t] += vv * Am[hg * 16 + t][i];
    }
    const float g = *gptr;
#pragma unroll
    for (int t = 0; t < 16; t++) {
        int h = hg * 16 + t;
        size_t idx = (size_t)((b * 512 + cbk + tc) * 64 + h) * 64 + w;
        fout[idx] = fin[idx] + g * acc[t];
    }
}

// aggW additionally produces the bf16 hi/lo NHWC planes of the final value
__global__ void __launch_bounds__(256) aggW_kernel(
    const float* __restrict__ v, const float* __restrict__ attn,
    float* __restrict__ fout, const float* __restrict__ gptr,
    __nv_bfloat16* __restrict__ Dhi, __nv_bfloat16* __restrict__ Dlo)
{
    const int h = blockIdx.x, b = blockIdx.y, cbk = blockIdx.z * 64;
    __shared__ float Vs[64][65];
    __shared__ float Am[64][65];
    const int tid = threadIdx.x;
    for (int l = tid; l < 4096; l += 256) {
        int c = l >> 6, j = l & 63;
        Vs[c][j] = v[(size_t)((b * 512 + cbk + c) * 64 + h) * 64 + j];
    }
    for (int l = tid; l < 4096; l += 256) {
        int w = l >> 6, j = l & 63;
        Am[w][j] = attn[(size_t)(((b * 64 + h) * 64 + w)) * 128 + 64 + j];
    }
    __syncthreads();
    const int tc = tid & 63, wg = tid >> 6;
    float acc[16];
#pragma unroll
    for (int t = 0; t < 16; t++) acc[t] = 0.f;
    for (int j = 0; j < 64; j++) {
        float vv = Vs[tc][j];
#pragma unroll
        for (int t = 0; t < 16; t++) acc[t] += vv * Am[wg * 16 + t][j];
    }
    const float g = *gptr;
#pragma unroll
    for (int t = 0; t < 16; t++) {
        int w = wg * 16 + t;
        size_t idx = (size_t)((b * 512 + cbk + tc) * 64 + h) * 64 + w;
        float val = fout[idx] + g * acc[t];
        fout[idx] = val;
        __nv_bfloat16 hh, ll;
        split_bf16(val, hh, ll);
        size_t o = ((size_t)(b * HW_ + h * 64 + w)) * 512 + cbk + tc;
        Dhi[o] = hh;
        Dlo[o] = ll;
    }
}

// ---------------------------------------------------------------------------
// Launch
// ---------------------------------------------------------------------------
extern "C" void kernel_launch(void* const* d_in, const int* in_sizes, int n_in,
                              void* d_out, int out_size)
{
    const float* x     = (const float*)d_in[0];
    const float* c1w   = (const float*)d_in[1];
    const float* bn1g  = (const float*)d_in[2];
    const float* bn1b  = (const float*)d_in[3];
    const float* bn1m  = (const float*)d_in[4];
    const float* bn1v  = (const float*)d_in[5];
    const float* qw    = (const float*)d_in[6];
    const float* qb    = (const float*)d_in[7];
    const float* kw    = (const float*)d_in[8];
    const float* kb    = (const float*)d_in[9];
    const float* vw    = (const float*)d_in[10];
    const float* vb    = (const float*)d_in[11];
    const float* gamma = (const float*)d_in[12];
    const float* c2w   = (const float*)d_in[13];
    const float* bn2g  = (const float*)d_in[14];
    const float* bn2b  = (const float*)d_in[15];
    const float* bn2m  = (const float*)d_in[16];
    const float* bn2v  = (const float*)d_in[17];
    float* out = (float*)d_out;

    float *fA, *fB, *gv, *gqk, *gat, *gbqk;
    __nv_bfloat16 *xhi, *xlo, *fhi, *flo, *w1hi, *w1lo, *w2hi, *w2lo, *wqkhi, *wqklo, *wvhi, *wvlo;
    cudaGetSymbolAddress((void**)&fA, g_featsA);
    cudaGetSymbolAddress((void**)&fB, g_featsB);
    cudaGetSymbolAddress((void**)&gv, g_v);
    cudaGetSymbolAddress((void**)&gqk, g_qk);
    cudaGetSymbolAddress((void**)&gat, g_attn);
    cudaGetSymbolAddress((void**)&gbqk, g_bqk);
    cudaGetSymbolAddress((void**)&xhi, g_xhi);
    cudaGetSymbolAddress((void**)&xlo, g_xlo);
    cudaGetSymbolAddress((void**)&fhi, g_fhi);
    cudaGetSymbolAddress((void**)&flo, g_flo);
    cudaGetSymbolAddress((void**)&w1hi, g_w1hi);
    cudaGetSymbolAddress((void**)&w1lo, g_w1lo);
    cudaGetSymbolAddress((void**)&w2hi, g_w2hi);
    cudaGetSymbolAddress((void**)&w2lo, g_w2lo);
    cudaGetSymbolAddress((void**)&wqkhi, g_wqkhi);
    cudaGetSymbolAddress((void**)&wqklo, g_wqklo);
    cudaGetSymbolAddress((void**)&wvhi, g_wvhi);
    cudaGetSymbolAddress((void**)&wvlo, g_wvlo);

    const int SMEM_CG2 = 2 * 98304 + 1024;
    const int SMEM_P1  = 2 * (2 * 128 * 128 + 2 * 128 * 128) + 1024;
    cudaFuncSetAttribute(mma_conv_cg2<2048, 9, 1, 1>, cudaFuncAttributeMaxDynamicSharedMemorySize, SMEM_CG2);
    cudaFuncSetAttribute(mma_conv_cg2<512, 9, 1, 0>,  cudaFuncAttributeMaxDynamicSharedMemorySize, SMEM_CG2);
    cudaFuncSetAttribute(mma_conv_cg2<512, 1, 0, 0>,  cudaFuncAttributeMaxDynamicSharedMemorySize, SMEM_CG2);
    cudaFuncSetAttribute(mma_proj_cg1<512, 0>,        cudaFuncAttributeMaxDynamicSharedMemorySize, SMEM_P1);

    // launch order chosen so the ncu capture window lands on conv1 (index ~2)
    prep_wconv<<<(512 * 2048 + 255) / 256, 256>>>(c1w, w1hi, w1lo, 512, 2048);       // 0
    prep_act<<<dim3(128, 64, 4), dim3(32, 8)>>>(x, xhi, xlo, 2048);                  // 1
    mma_conv_cg2<2048, 9, 1, 1><<<dim3(4, 32), 256, SMEM_CG2>>>(                     // 2: conv1
        w1hi, w1lo, xhi, xlo, bn1g, bn1b, bn1m, bn1v, fA, fhi, flo, 512);
    prep_wqk<<<256, 256>>>(qw, kw, qb, kb, wqkhi, wqklo, gbqk);                      // 3
    prep_wlin<<<(512 * 512 + 255) / 256, 256>>>(vw, wvhi, wvlo, 512 * 512);          // 4
    prep_wconv<<<(512 * 512 + 255) / 256, 256>>>(c2w, w2hi, w2lo, 512, 512);         // 5

    // --- 2x criss-cross attention (fhi/flo produced by conv1 / previous aggW) ---
    float* cur = fA;
    float* nxt = fB;
    for (int it = 0; it < 2; ++it) {
        mma_proj_cg1<512, 0><<<dim3(1, 128), 256, SMEM_P1>>>(
            wqkhi, wqklo, fhi, flo, gbqk, gqk, 128);
        mma_conv_cg2<512, 1, 0, 0><<<dim3(4, 32), 256, SMEM_CG2>>>(
            wvhi, wvlo, fhi, flo, vb, nullptr, nullptr, nullptr, gv, nullptr, nullptr, 512);
        energyH_kernel<<<dim3(64, 4), 256>>>(gqk, gat);
        energyW_kernel<<<dim3(64, 4), 256>>>(gqk, gat);
        softmax_kernel<<<NPIX_ / 8, 256>>>(gat);
        aggH_kernel<<<dim3(64, 4, 8), 256>>>(gv, gat, cur, nxt, gamma);
        aggW_kernel<<<dim3(64, 4, 8), 256>>>(gv, gat, nxt, gamma, fhi, flo);
        float* tmp = cur; cur = nxt; nxt = tmp;
    }

    // --- conv2 + BN + ReLU (reads fhi/flo from the last aggW) ---
    mma_conv_cg2<512, 9, 1, 0><<<dim3(4, 32), 256, SMEM_CG2>>>(
        w2hi, w2lo, fhi, flo, bn2g, bn2b, bn2m, bn2v, out, nullptr, nullptr, 512);
}

// round 6
// speedup vs baseline: 1.6336x; 1.6336x over previous
#include <cuda_runtime.h>
#include <cuda_fp16.h>
#include <math.h>
#include <stdint.h>

#define HW_   4096
#define NPIX_ 16384

// tcgen05 exists only in the arch-specific (sm_103a/sm_100a) pass.
#if defined(__CUDA_ARCH__) && (defined(__CUDA_ARCH_FEAT_SM103_ALL) || defined(__CUDA_ARCH_FEAT_SM100_ALL))
#define HAS_TC 1
#else
#define HAS_TC 0
#endif

#define WSCALE     64.0f
#define INV_WSCALE 0.015625f

// ---------------------------------------------------------------------------
// Scratch (device globals; allocation is forbidden)
// ---------------------------------------------------------------------------
__device__ float g_featsA[4 * 512 * 4096];
__device__ float g_featsB[4 * 512 * 4096];
__device__ float g_v[4 * 512 * 4096];
__device__ float g_qk[4 * 128 * 4096];
__device__ float g_attn[4 * 4096 * 128];
__device__ float g_bqk[128];
__device__ __half g_xh[4 * 4096 * 2048];     // conv1 input, NHWC fp16
__device__ __half g_fh[4 * 4096 * 512];      // feats, NHWC fp16
__device__ __half g_w1hi[9 * 512 * 2048];
__device__ __half g_w1lo[9 * 512 * 2048];
__device__ __half g_w2hi[9 * 512 * 512];
__device__ __half g_w2lo[9 * 512 * 512];
__device__ __half g_wqkhi[128 * 512];
__device__ __half g_wqklo[128 * 512];
__device__ __half g_wvhi[512 * 512];
__device__ __half g_wvlo[512 * 512];

// ---------------------------------------------------------------------------
// Generic helpers (valid on base sm_103)
// ---------------------------------------------------------------------------
__device__ __forceinline__ unsigned smem_u32(const void* p) {
    unsigned a;
    asm("{ .reg .u64 t; cvta.to.shared.u64 t, %1; cvt.u32.u64 %0, t; }"
        : "=r"(a) : "l"(p));
    return a;
}
__device__ __forceinline__ unsigned elect_one() {
    unsigned p;
    asm volatile("{ .reg .pred p; elect.sync _|p, 0xFFFFFFFF; selp.b32 %0, 1, 0, p; }"
                 : "=r"(p));
    return p;
}
#define SW128(o) ((o) ^ (((o) >> 3) & 0x70))
__device__ __forceinline__ void mbar_init(unsigned mbar, unsigned cnt) {
    asm volatile("mbarrier.init.shared.b64 [%0], %1;" :: "r"(mbar), "r"(cnt) : "memory");
}
__device__ __forceinline__ void mbar_wait(unsigned mbar, unsigned phase) {
    asm volatile(
        "{\n\t.reg .pred P;\n\t"
        "WL_%=:\n\t"
        "mbarrier.try_wait.parity.acquire.cta.shared::cta.b64 P, [%0], %1, 0x989680;\n\t"
        "@P bra.uni WD_%=;\n\t"
        "bra.uni WL_%=;\n\t"
        "WD_%=:\n\t}"
        :: "r"(mbar), "r"(phase) : "memory");
}
__device__ __forceinline__ void fence_async_shared() {
    asm volatile("fence.proxy.async;" ::: "memory");
}

// ---------------------------------------------------------------------------
// tcgen05 / cluster helpers (arch-specific pass only)
// ---------------------------------------------------------------------------
#if HAS_TC
static constexpr unsigned long long SMEM_DESC_BASE_SW128 =
    (2ull << 61) | (1ull << 46) | (64ull << 32) | (1ull << 16);
__device__ __forceinline__ unsigned long long make_desc(unsigned addr) {
    return SMEM_DESC_BASE_SW128 | ((unsigned long long)(addr >> 4) & 0x3FFFull);
}
__device__ __forceinline__ void mbar_wait_cluster(unsigned mbar, unsigned phase) {
    asm volatile(
        "{\n\t.reg .pred P;\n\t"
        "WL_%=:\n\t"
        "mbarrier.try_wait.parity.acquire.cluster.shared::cta.b64 P, [%0], %1, 0x989680;\n\t"
        "@P bra.uni WD_%=;\n\t"
        "bra.uni WL_%=;\n\t"
        "WD_%=:\n\t}"
        :: "r"(mbar), "r"(phase) : "memory");
}
__device__ __forceinline__ void mbar_arrive_rank0(unsigned local_addr) {
    asm volatile(
        "{\n\t.reg .b32 r;\n\t"
        "mapa.shared::cluster.u32 r, %0, 0;\n\t"
        "mbarrier.arrive.shared::cluster.b64 _, [r];\n\t}"
        :: "r"(local_addr) : "memory");
}
__device__ __forceinline__ void cluster_sync_() {
    asm volatile("barrier.cluster.arrive.aligned;" ::: "memory");
    asm volatile("barrier.cluster.wait.aligned;" ::: "memory");
}
__device__ __forceinline__ void tmem_alloc_cg1(unsigned dst_smem, unsigned ncols) {
    asm volatile("tcgen05.alloc.cta_group::1.sync.aligned.shared::cta.b32 [%0], %1;"
                 :: "r"(dst_smem), "r"(ncols) : "memory");
}
__device__ __forceinline__ void tmem_dealloc_cg1(unsigned tmem, unsigned ncols) {
    asm volatile("tcgen05.dealloc.cta_group::1.sync.aligned.b32 %0, %1;"
                 :: "r"(tmem), "r"(ncols));
}
__device__ __forceinline__ void tmem_alloc_cg2(unsigned dst_smem, unsigned ncols) {
    asm volatile("tcgen05.alloc.cta_group::2.sync.aligned.shared::cta.b32 [%0], %1;"
                 :: "r"(dst_smem), "r"(ncols) : "memory");
}
__device__ __forceinline__ void tmem_dealloc_cg2(unsigned tmem, unsigned ncols) {
    asm volatile("tcgen05.dealloc.cta_group::2.sync.aligned.b32 %0, %1;"
                 :: "r"(tmem), "r"(ncols));
}
__device__ __forceinline__ void tc_relinquish_cg2() {
    asm volatile("tcgen05.relinquish_alloc_permit.cta_group::2.sync.aligned;");
}
__device__ __forceinline__ void tc_commit_cg1(unsigned mbar) {
    asm volatile("tcgen05.commit.cta_group::1.mbarrier::arrive::one.shared::cluster.b64 [%0];"
                 :: "r"(mbar) : "memory");
}
__device__ __forceinline__ void tc_commit_mc_cg2(unsigned mbar, unsigned short mask) {
    asm volatile("tcgen05.commit.cta_group::2.mbarrier::arrive::one.shared::cluster.multicast::cluster.b64 [%0], %1;"
                 :: "r"(mbar), "h"(mask) : "memory");
}
__device__ __forceinline__ void tc_fence_after() {
    asm volatile("tcgen05.fence::after_thread_sync;" ::: "memory");
}
__device__ __forceinline__ void tc_wait_ld() {
    asm volatile("tcgen05.wait::ld.sync.aligned;" ::: "memory");
}
// fp16 MMA (atype=btype=F16=0), fp32 accumulate
__device__ __forceinline__ void mma_cg1(unsigned d, unsigned long long ad,
                                        unsigned long long bd, unsigned idesc, unsigned en) {
    asm volatile(
        "{\n\t.reg .pred p;\n\tsetp.ne.u32 p, %4, 0;\n\t"
        "tcgen05.mma.cta_group::1.kind::f16 [%0], %1, %2, %3, {%5, %5, %5, %5}, p;\n\t}"
        :: "r"(d), "l"(ad), "l"(bd), "r"(idesc), "r"(en), "r"(0u) : "memory");
}
__device__ __forceinline__ void mma_cg2(unsigned d, unsigned long long ad,
                                        unsigned long long bd, unsigned idesc, unsigned en) {
    asm volatile(
        "{\n\t.reg .pred p;\n\tsetp.ne.u32 p, %4, 0;\n\t"
        "tcgen05.mma.cta_group::2.kind::f16 [%0], %1, %2, %3, "
        "{%5, %5, %5, %5, %5, %5, %5, %5}, p;\n\t}"
        :: "r"(d), "l"(ad), "l"(bd), "r"(idesc), "r"(en), "r"(0u) : "memory");
}
__device__ __forceinline__ void tmem_ld32(unsigned* r, unsigned addr) {
    asm volatile(
        "tcgen05.ld.sync.aligned.32x32b.x32.b32 "
        "{%0, %1, %2, %3, %4, %5, %6, %7, "
        " %8, %9, %10, %11, %12, %13, %14, %15, "
        " %16, %17, %18, %19, %20, %21, %22, %23, "
        " %24, %25, %26, %27, %28, %29, %30, %31}, [%32];"
        : "=r"(r[0]),  "=r"(r[1]),  "=r"(r[2]),  "=r"(r[3]),
          "=r"(r[4]),  "=r"(r[5]),  "=r"(r[6]),  "=r"(r[7]),
          "=r"(r[8]),  "=r"(r[9]),  "=r"(r[10]), "=r"(r[11]),
          "=r"(r[12]), "=r"(r[13]), "=r"(r[14]), "=r"(r[15]),
          "=r"(r[16]), "=r"(r[17]), "=r"(r[18]), "=r"(r[19]),
          "=r"(r[20]), "=r"(r[21]), "=r"(r[22]), "=r"(r[23]),
          "=r"(r[24]), "=r"(r[25]), "=r"(r[26]), "=r"(r[27]),
          "=r"(r[28]), "=r"(r[29]), "=r"(r[30]), "=r"(r[31])
        : "r"(addr));
}
__device__ __forceinline__ void cp16(unsigned dst, const void* src, unsigned bytes) {
    asm volatile("cp.async.cg.shared.global [%0], [%1], 16, %2;"
                 :: "r"(dst), "l"(src), "r"(bytes) : "memory");
}
__device__ __forceinline__ void cp_commit_wait0() {
    asm volatile("cp.async.commit_group;" ::: "memory");
    asm volatile("cp.async.wait_group 0;" ::: "memory");
}
#endif

// ---------------------------------------------------------------------------
// Prep kernels
// ---------------------------------------------------------------------------
__device__ __forceinline__ void split_half(float x, __half& h, __half& l) {
    h = __float2half(x);
    l = __float2half(x - __half2float(h));
}

// NCHW fp32 -> NHWC fp16 (single plane)
__global__ void prep_act(const float* __restrict__ src,
                         __half* __restrict__ dh, int CIN) {
    __shared__ float t[32][33];
    const int b = blockIdx.z, ct = blockIdx.y * 32, pt = blockIdx.x * 32;
    const int tx = threadIdx.x, ty = threadIdx.y;
    for (int i = ty; i < 32; i += 8)
        t[i][tx] = src[((size_t)(b * CIN + ct + i)) * HW_ + pt + tx];
    __syncthreads();
    for (int i = ty; i < 32; i += 8) {
        size_t o = ((size_t)(b * HW_ + pt + i)) * CIN + ct + tx;
        dh[o] = __float2half(t[tx][i]);
    }
}

// OIHW fp32 conv weights -> [tap][m][cin] fp16 hi/lo, prescaled by WSCALE
__global__ void prep_wconv(const float* __restrict__ W,
                           __half* __restrict__ dhi,
                           __half* __restrict__ dlo, int M, int CIN) {
    int idx = blockIdx.x * 256 + threadIdx.x;
    if (idx >= M * CIN) return;
#pragma unroll
    for (int tap = 0; tap < 9; tap++) {
        float x = W[(size_t)idx * 9 + tap] * WSCALE;
        __half h, l;
        split_half(x, h, l);
        size_t o = (size_t)tap * M * CIN + idx;
        dhi[o] = h;
        dlo[o] = l;
    }
}

__global__ void prep_wlin(const float* __restrict__ W,
                          __half* __restrict__ dhi,
                          __half* __restrict__ dlo, int n) {
    int i = blockIdx.x * 256 + threadIdx.x;
    if (i >= n) return;
    __half h, l;
    split_half(W[i] * WSCALE, h, l);
    dhi[i] = h;
    dlo[i] = l;
}

// q/k weight stack (M=128) + stacked bias, one launch
__global__ void prep_wqk(const float* __restrict__ qw, const float* __restrict__ kw,
                         const float* __restrict__ qb, const float* __restrict__ kb,
                         __half* __restrict__ dhi, __half* __restrict__ dlo,
                         float* __restrict__ bias) {
    int i = blockIdx.x * 256 + threadIdx.x;
    if (i < 128) bias[i] = (i < 64) ? qb[i] : kb[i - 64];
    if (i >= 128 * 512) return;
    float x = ((i < 64 * 512) ? qw[i] : kw[i - 64 * 512]) * WSCALE;
    __half h, l;
    split_half(x, h, l);
    dhi[i] = h;
    dlo[i] = l;
}

// ---------------------------------------------------------------------------
// cg2 implicit-conv GEMM: M=256 per cluster (128/CTA), 4 n-tiles (512 px),
// fp16 2-MMA scheme: D = (A_hi + A_lo) * B_h16, fp32 TMEM accumulate.
// ---------------------------------------------------------------------------
template<int CIN, int TAPS, int EPI>
__global__ void __launch_bounds__(256, 1) __cluster_dims__(2, 1, 1)
mma_conv_cg2(const __half* __restrict__ Whi, const __half* __restrict__ Wlo,
             const __half* __restrict__ Xh,
             const float* __restrict__ e0, const float* __restrict__ e1,
             const float* __restrict__ e2, const float* __restrict__ e3,
             float* __restrict__ Y, int Mtot)
{
#if HAS_TC
    constexpr int NCHUNK = TAPS * (CIN / 64);
    constexpr int A_HI = 0;            // 128 rows x 128B
    constexpr int A_LO = 16384;
    constexpr int B_0  = 32768;        // 4 tiles x 64 rows x 128B = 32KB
    constexpr int STAGE = 65536;       // 64 KB
    constexpr unsigned IDESC2 = (1u << 4) | (16u << 17) | (16u << 24); // f32 acc, f16, N=128, M=256

    extern __shared__ char dyn_smem[];
    __shared__ __align__(8) unsigned long long s_full[2];
    __shared__ __align__(8) unsigned long long s_done[2];
    __shared__ unsigned s_tmem[1];

    char* sm = (char*)((((uintptr_t)dyn_smem) + 1023) & ~(uintptr_t)1023);
    const unsigned sbase = smem_u32(sm);

    const int tid  = threadIdx.x;
    const int wid  = tid >> 5;
    const int lane = tid & 31;
    const unsigned rank = blockIdx.x & 1;
    const int m_base = (blockIdx.x >> 1) * 256;
    const int n_base = blockIdx.y * 512;
    const int bb   = n_base >> 12;
    const int sp00 = n_base & 4095;

    if (wid == 0) tmem_alloc_cg2(smem_u32(&s_tmem[0]), 512);
    if (tid == 0) {
        mbar_init(smem_u32(&s_full[0]), 2);
        mbar_init(smem_u32(&s_full[1]), 2);
        mbar_init(smem_u32(&s_done[0]), 1);
        mbar_init(smem_u32(&s_done[1]), 1);
    }
    __syncthreads();
    unsigned tmem;
    asm volatile("ld.shared.b32 %0, [%1];" : "=r"(tmem) : "r"(smem_u32(&s_tmem[0])));
    const unsigned fullb[2] = { smem_u32(&s_full[0]), smem_u32(&s_full[1]) };
    const unsigned doneb[2] = { smem_u32(&s_done[0]), smem_u32(&s_done[1]) };
    cluster_sync_();

    int dph[2] = {0, 0};
    int fph[2] = {0, 0};

    for (int chunk = 0; chunk < NCHUNK; ++chunk) {
        const int s   = chunk & 1;
        const int tap = (TAPS == 1) ? 0 : chunk / (CIN / 64);
        const int cb  = (TAPS == 1) ? chunk * 64 : (chunk % (CIN / 64)) * 64;
        const int dh  = (TAPS == 9) ? (tap / 3 - 1) : 0;
        const int dw  = (TAPS == 9) ? (tap % 3 - 1) : 0;

        if (chunk >= 2) { mbar_wait(doneb[s], dph[s]); dph[s] ^= 1; }

        const unsigned stg = sbase + s * STAGE;

        {   // A: this CTA's 128 M-rows x 64 ch, hi + lo
            const __half* srcH = Whi + ((size_t)tap * Mtot + m_base + rank * 128) * CIN + cb;
            const __half* srcL = Wlo + ((size_t)tap * Mtot + m_base + rank * 128) * CIN + cb;
#pragma unroll
            for (int u = 0; u < 4; ++u) {
                int l = u * 256 + tid;
                int row = l >> 3, c16 = l & 7;
                size_t go = (size_t)row * CIN + c16 * 8;
                unsigned so = SW128((unsigned)(row * 128 + c16 * 16));
                cp16(stg + A_HI + so, srcH + go, 16);
                cp16(stg + A_LO + so, srcL + go, 16);
            }
        }
        {   // B: 4 n-tiles, this CTA's 64-row half, tap-shifted, zfill OOB (single plane)
#pragma unroll
            for (int u = 0; u < 8; ++u) {
                int l = u * 256 + tid;
                int t = l >> 9, r = (l >> 3) & 63, c16 = l & 7;
                int sp = sp00 + t * 128 + (int)rank * 64 + r;
                int h = (sp >> 6) + dh, w = (sp & 63) + dw;
                bool ok = ((unsigned)h < 64u) && ((unsigned)w < 64u);
                unsigned bytes = ok ? 16u : 0u;
                size_t go = ((size_t)(bb * HW_ + (ok ? h * 64 + w : 0))) * CIN + cb + c16 * 8;
                unsigned so = SW128((unsigned)(r * 128 + c16 * 16));
                cp16(stg + B_0 + t * 8192 + so, Xh + go, bytes);
            }
        }
        cp_commit_wait0();
        __syncthreads();
        if (tid == 0) {
            fence_async_shared();
            mbar_arrive_rank0(fullb[s]);
        }
        if (rank == 0 && wid == 0 && elect_one()) {
            mbar_wait_cluster(fullb[s], fph[s]); fph[s] ^= 1;
            unsigned long long dAh = make_desc(stg + A_HI);
            unsigned long long dAl = make_desc(stg + A_LO);
#pragma unroll
            for (int t = 0; t < 4; ++t) {
                unsigned d = tmem + t * 128;
                unsigned long long dB = make_desc(stg + B_0 + t * 8192);
#pragma unroll
                for (int kk = 0; kk < 4; ++kk) {
                    unsigned en0 = (chunk > 0 || kk > 0) ? 1u : 0u;
                    mma_cg2(d, dAh + kk * 2, dB + kk * 2, IDESC2, en0);
                    mma_cg2(d, dAl + kk * 2, dB + kk * 2, IDESC2, 1u);
                }
            }
            tc_commit_mc_cg2(doneb[s], 0x3);
        }
    }

    {
        int s0 = (NCHUNK - 2) & 1, s1 = (NCHUNK - 1) & 1;
        mbar_wait(doneb[s0], dph[s0]); dph[s0] ^= 1;
        mbar_wait(doneb[s1], dph[s1]); dph[s1] ^= 1;
    }
    tc_fence_after();

    // --- epilogue (acc carries x WSCALE; fold 1/WSCALE into scale) ---
    {
        const int wg = wid >> 2;
        const int mg = m_base + (int)rank * 128 + (wid & 3) * 32 + lane;
        float sc, sh;
        if (EPI == 1) {
            float tt = e0[mg] * rsqrtf(e3[mg] + 1e-5f);
            sc = tt * INV_WSCALE;
            sh = e1[mg] - e2[mg] * tt;
        } else {
            sc = INV_WSCALE;
            sh = e0[mg];
        }
        float* yrow = Y + ((size_t)(bb * Mtot + mg)) * HW_ + sp00;
#pragma unroll
        for (int ti = 0; ti < 2; ++ti) {
            int t = wg * 2 + ti;
#pragma unroll
            for (int cb4 = 0; cb4 < 4; ++cb4) {
                unsigned r[32];
                tmem_ld32(r, tmem + t * 128 + cb4 * 32);
                tc_wait_ld();
#pragma unroll
                for (int j = 0; j < 32; j += 4) {
                    float4 v;
                    v.x = fmaf(__uint_as_float(r[j + 0]), sc, sh);
                    v.y = fmaf(__uint_as_float(r[j + 1]), sc, sh);
                    v.z = fmaf(__uint_as_float(r[j + 2]), sc, sh);
                    v.w = fmaf(__uint_as_float(r[j + 3]), sc, sh);
                    if (EPI == 1) {
                        v.x = fmaxf(v.x, 0.f); v.y = fmaxf(v.y, 0.f);
                        v.z = fmaxf(v.z, 0.f); v.w = fmaxf(v.w, 0.f);
                    }
                    *(float4*)(yrow + t * 128 + cb4 * 32 + j) = v;
                }
            }
        }
    }
    __syncthreads();
    if (wid == 0) {
        tc_relinquish_cg2();
        tmem_dealloc_cg2(tmem, 512);
    }
    cluster_sync_();
#endif
}

// ---------------------------------------------------------------------------
// cg1 GEMM for the stacked q/k projection (M=128), fp16 2-MMA scheme
// ---------------------------------------------------------------------------
template<int CIN>
__global__ void __launch_bounds__(256, 1)
mma_proj_cg1(const __half* __restrict__ Whi, const __half* __restrict__ Wlo,
             const __half* __restrict__ Xh,
             const float* __restrict__ e0, float* __restrict__ Y, int Mtot)
{
#if HAS_TC
    constexpr int A_BYTES = 128 * 128;   // 16KB per plane
    constexpr int B_BYTES = 128 * 128;   // 128 px x 128B
    constexpr int STAGE   = 2 * A_BYTES + B_BYTES;   // 48KB
    constexpr int NCHUNK  = CIN / 64;
    constexpr unsigned IDESC = (1u << 4) | (16u << 17) | (8u << 24);

    extern __shared__ char dyn_smem[];
    __shared__ __align__(8) unsigned long long s_mbar[2];
    __shared__ unsigned s_tmem[1];

    char* sm = (char*)((((uintptr_t)dyn_smem) + 1023) & ~(uintptr_t)1023);
    const unsigned sbase = smem_u32(sm);
    const int tid = threadIdx.x;
    const int wid = tid >> 5;
    const int lane = tid & 31;

    if (wid == 0) tmem_alloc_cg1(smem_u32(&s_tmem[0]), 256);
    if (tid == 0) { mbar_init(smem_u32(&s_mbar[0]), 1); mbar_init(smem_u32(&s_mbar[1]), 1); }
    __syncthreads();
    unsigned tmem;
    asm volatile("ld.shared.b32 %0, [%1];" : "=r"(tmem) : "r"(smem_u32(&s_tmem[0])));
    const unsigned mbar[2] = { smem_u32(&s_mbar[0]), smem_u32(&s_mbar[1]) };

    const int n_base = blockIdx.y * 128;
    const int bb  = n_base >> 12;
    const int sp0 = n_base & 4095;
    int ph[2] = {0, 0};

    for (int chunk = 0; chunk < NCHUNK; ++chunk) {
        const int s  = chunk & 1;
        const int cb = chunk * 64;
        if (chunk >= 2) { mbar_wait(mbar[s], ph[s]); ph[s] ^= 1; }

        char* aHi = sm + s * STAGE;
        char* aLo = aHi + A_BYTES;
        char* bH  = aLo + A_BYTES;
#pragma unroll
        for (int u = 0; u < 4; ++u) {
            int l = u * 256 + tid;
            int row = l >> 3, c16 = l & 7;
            size_t go = (size_t)row * CIN + cb + c16 * 8;
            unsigned so = SW128((unsigned)(row * 128 + c16 * 16));
            *(uint4*)(aHi + so) = *(const uint4*)(Whi + go);
            *(uint4*)(aLo + so) = *(const uint4*)(Wlo + go);
        }
#pragma unroll
        for (int u = 0; u < 4; ++u) {
            int l = u * 256 + tid;
            int row = l >> 3, c16 = l & 7;
            size_t go = ((size_t)(bb * HW_ + sp0 + row)) * CIN + cb + c16 * 8;
            unsigned so = SW128((unsigned)(row * 128 + c16 * 16));
            *(uint4*)(bH + so) = *(const uint4*)(Xh + go);
        }
        fence_async_shared();
        __syncthreads();

        if (wid == 0 && elect_one()) {
            unsigned long long dAh = make_desc(sbase + s * STAGE);
            unsigned long long dAl = dAh + (A_BYTES >> 4);
            unsigned long long dB  = make_desc(sbase + s * STAGE + 2 * A_BYTES);
#pragma unroll
            for (int kk = 0; kk < 4; ++kk) {
                unsigned en0 = (chunk > 0 || kk > 0) ? 1u : 0u;
                mma_cg1(tmem, dAh + kk * 2, dB + kk * 2, IDESC, en0);
                mma_cg1(tmem, dAl + kk * 2, dB + kk * 2, IDESC, 1u);
            }
            tc_commit_cg1(mbar[s]);
        }
    }
    {
        int s0 = (NCHUNK - 2) & 1, s1 = (NCHUNK - 1) & 1;
        mbar_wait(mbar[s0], ph[s0]); ph[s0] ^= 1;
        mbar_wait(mbar[s1], ph[s1]); ph[s1] ^= 1;
    }
    tc_fence_after();

    if (wid < 4) {
        const int mg = wid * 32 + lane;
        float sh = e0[mg];
        float* yrow = Y + ((size_t)(bb * Mtot + mg)) * HW_ + sp0;
#pragma unroll
        for (int cb4 = 0; cb4 < 4; ++cb4) {
            unsigned r[32];
            tmem_ld32(r, tmem + cb4 * 32);
            tc_wait_ld();
#pragma unroll
            for (int j = 0; j < 32; j += 4) {
                float4 v;
                v.x = fmaf(__uint_as_float(r[j + 0]), INV_WSCALE, sh);
                v.y = fmaf(__uint_as_float(r[j + 1]), INV_WSCALE, sh);
                v.z = fmaf(__uint_as_float(r[j + 2]), INV_WSCALE, sh);
                v.w = fmaf(__uint_as_float(r[j + 3]), INV_WSCALE, sh);
                *(float4*)(yrow + cb4 * 32 + j) = v;
            }
        }
    }
    __syncthreads();
    if (wid == 0) tmem_dealloc_cg1(tmem, 256);
#endif
}

// ---------------------------------------------------------------------------
// CCA kernels (fp32; proven since R1)
// ---------------------------------------------------------------------------
__global__ void __launch_bounds__(256) energyH_kernel(
    const float* __restrict__ qk, float* __restrict__ attn)
{
    const int w = blockIdx.x, b = blockIdx.y;
    __shared__ float Qs[64][65];
    __shared__ float Ks[64][65];
    const int tid = threadIdx.x;
    for (int l = tid; l < 4096; l += 256) {
        int c = l >> 6, h = l & 63;
        Qs[c][h] = qk[((size_t)(b * 128 + c)) * HW_ + h * 64 + w];
        Ks[c][h] = qk[((size_t)(b * 128 + 64 + c)) * HW_ + h * 64 + w];
    }
    __syncthreads();
    const int hh = tid & 63, ig = tid >> 6;
    float acc[16];
#pragma unroll
    for (int i = 0; i < 16; i++) acc[i] = 0.f;
    for (int c = 0; c < 64; c++) {
        float qv = Qs[c][hh];
#pragma unroll
        for (int i = 0; i < 16; i++) acc[i] += qv * Ks[c][ig * 16 + i];
    }
    float* orow = attn + (size_t)(((b * 64 + hh) * 64 + w)) * 128;
#pragma unroll
    for (int i = 0; i < 16; i++) {
        int ii = ig * 16 + i;
        orow[ii] = acc[i] + ((ii == hh) ? -1000000000.0f : 0.f);
    }
}

__global__ void __launch_bounds__(256) energyW_kernel(
    const float* __restrict__ qk, float* __restrict__ attn)
{
    const int h = blockIdx.x, b = blockIdx.y;
    __shared__ float Qs[64][65];
    __shared__ float Ks[64][65];
    const int tid = threadIdx.x;
    for (int l = tid; l < 4096; l += 256) {
        int c = l >> 6, w = l & 63;
        Qs[c][w] = qk[((size_t)(b * 128 + c)) * HW_ + h * 64 + w];
        Ks[c][w] = qk[((size_t)(b * 128 + 64 + c)) * HW_ + h * 64 + w];
    }
    __syncthreads();
    const int wq = tid & 63, jg = tid >> 6;
    float acc[16];
#pragma unroll
    for (int j = 0; j < 16; j++) acc[j] = 0.f;
    for (int c = 0; c < 64; c++) {
        float qv = Qs[c][wq];
#pragma unroll
        for (int j = 0; j < 16; j++) acc[j] += qv * Ks[c][jg * 16 + j];
    }
    float* orow = attn + (size_t)(((b * 64 + h) * 64 + wq)) * 128 + 64;
#pragma unroll
    for (int j = 0; j < 16; j++) orow[jg * 16 + j] = acc[j];
}

__global__ void __launch_bounds__(256) softmax_kernel(float* __restrict__ attn)
{
    int gw = (blockIdx.x * blockDim.x + threadIdx.x) >> 5;
    if (gw >= NPIX_) return;
    int lane = threadIdx.x & 31;
    float* row = attn + (size_t)gw * 128;
    float v0 = row[lane], v1 = row[lane + 32], v2 = row[lane + 64], v3 = row[lane + 96];
    float mx = fmaxf(fmaxf(v0, v1), fmaxf(v2, v3));
#pragma unroll
    for (int o = 16; o > 0; o >>= 1) mx = fmaxf(mx, __shfl_xor_sync(0xffffffffu, mx, o));
    v0 = expf(v0 - mx); v1 = expf(v1 - mx); v2 = expf(v2 - mx); v3 = expf(v3 - mx);
    float s = v0 + v1 + v2 + v3;
#pragma unroll
    for (int o = 16; o > 0; o >>= 1) s += __shfl_xor_sync(0xffffffffu, s, o);
    float inv = 1.0f / s;
    row[lane] = v0 * inv; row[lane + 32] = v1 * inv;
    row[lane + 64] = v2 * inv; row[lane + 96] = v3 * inv;
}

__global__ void __launch_bounds__(256) aggH_kernel(
    const float* __restrict__ v, const float* __restrict__ attn,
    const float* __restrict__ fin, float* __restrict__ fout,
    const float* __restrict__ gptr)
{
    const int w = blockIdx.x, b = blockIdx.y, cbk = blockIdx.z * 64;
    __shared__ float Vs[64][65];
    __shared__ float Am[64][65];
    const int tid = threadIdx.x;
    for (int l = tid; l < 4096; l += 256) {
        int c = l >> 6, i = l & 63;
        Vs[c][i] = v[(size_t)((b * 512 + cbk + c) * 64 + i) * 64 + w];
    }
    for (int l = tid; l < 4096; l += 256) {
        int h = l >> 6, i = l & 63;
        Am[h][i] = attn[(size_t)(((b * 64 + h) * 64 + w)) * 128 + i];
    }
    __syncthreads();
    const int tc = tid & 63, hg = tid >> 6;
    float acc[16];
#pragma unroll
    for (int t = 0; t < 16; t++) acc[t] = 0.f;
    for (int i = 0; i < 64; i++) {
        float vv = Vs[tc][i];
#pragma unroll
        for (int t = 0; t < 16; t++) acc[t] += vv * Am[hg * 16 + t][i];
    }
    const float g = *gptr;
#pragma unroll
    for (int t = 0; t < 16; t++) {
        int h = hg * 16 + t;
        size_t idx = (size_t)((b * 512 + cbk + tc) * 64 + h) * 64 + w;
        fout[idx] = fin[idx] + g * acc[t];
    }
}

__global__ void __launch_bounds__(256) aggW_kernel(
    const float* __restrict__ v, const float* __restrict__ attn,
    float* __restrict__ fout, const float* __restrict__ gptr)
{
    const int h = blockIdx.x, b = blockIdx.y, cbk = blockIdx.z * 64;
    __shared__ float Vs[64][65];
    __shared__ float Am[64][65];
    const int tid = threadIdx.x;
    for (int l = tid; l < 4096; l += 256) {
        int c = l >> 6, j = l & 63;
        Vs[c][j] = v[(size_t)((b * 512 + cbk + c) * 64 + h) * 64 + j];
    }
    for (int l = tid; l < 4096; l += 256) {
        int w = l >> 6, j = l & 63;
        Am[w][j] = attn[(size_t)(((b * 64 + h) * 64 + w)) * 128 + 64 + j];
    }
    __syncthreads();
    const int tc = tid & 63, wg = tid >> 6;
    float acc[16];
#pragma unroll
    for (int t = 0; t < 16; t++) acc[t] = 0.f;
    for (int j = 0; j < 64; j++) {
        float vv = Vs[tc][j];
#pragma unroll
        for (int t = 0; t < 16; t++) acc[t] += vv * Am[wg * 16 + t][j];
    }
    const float g = *gptr;
#pragma unroll
    for (int t = 0; t < 16; t++) {
        int w = wg * 16 + t;
        size_t idx = (size_t)((b * 512 + cbk + tc) * 64 + h) * 64 + w;
        fout[idx] += g * acc[t];
    }
}

// ---------------------------------------------------------------------------
// Launch
// ---------------------------------------------------------------------------
extern "C" void kernel_launch(void* const* d_in, const int* in_sizes, int n_in,
                              void* d_out, int out_size)
{
    const float* x     = (const float*)d_in[0];
    const float* c1w   = (const float*)d_in[1];
    const float* bn1g  = (const float*)d_in[2];
    const float* bn1b  = (const float*)d_in[3];
    const float* bn1m  = (const float*)d_in[4];
    const float* bn1v  = (const float*)d_in[5];
    const float* qw    = (const float*)d_in[6];
    const float* qb    = (const float*)d_in[7];
    const float* kw    = (const float*)d_in[8];
    const float* kb    = (const float*)d_in[9];
    const float* vw    = (const float*)d_in[10];
    const float* vb    = (const float*)d_in[11];
    const float* gamma = (const float*)d_in[12];
    const float* c2w   = (const float*)d_in[13];
    const float* bn2g  = (const float*)d_in[14];
    const float* bn2b  = (const float*)d_in[15];
    const float* bn2m  = (const float*)d_in[16];
    const float* bn2v  = (const float*)d_in[17];
    float* out = (float*)d_out;

    float *fA, *fB, *gv, *gqk, *gat, *gbqk;
    __half *xh, *fh, *w1hi, *w1lo, *w2hi, *w2lo, *wqkhi, *wqklo, *wvhi, *wvlo;
    cudaGetSymbolAddress((void**)&fA, g_featsA);
    cudaGetSymbolAddress((void**)&fB, g_featsB);
    cudaGetSymbolAddress((void**)&gv, g_v);
    cudaGetSymbolAddress((void**)&gqk, g_qk);
    cudaGetSymbolAddress((void**)&gat, g_attn);
    cudaGetSymbolAddress((void**)&gbqk, g_bqk);
    cudaGetSymbolAddress((void**)&xh, g_xh);
    cudaGetSymbolAddress((void**)&fh, g_fh);
    cudaGetSymbolAddress((void**)&w1hi, g_w1hi);
    cudaGetSymbolAddress((void**)&w1lo, g_w1lo);
    cudaGetSymbolAddress((void**)&w2hi, g_w2hi);
    cudaGetSymbolAddress((void**)&w2lo, g_w2lo);
    cudaGetSymbolAddress((void**)&wqkhi, g_wqkhi);
    cudaGetSymbolAddress((void**)&wqklo, g_wqklo);
    cudaGetSymbolAddress((void**)&wvhi, g_wvhi);
    cudaGetSymbolAddress((void**)&wvlo, g_wvlo);

    const int SMEM_CG2 = 2 * 65536 + 1024;  // 132096
    const int SMEM_P1  = 2 * 49152 + 1024;  //  99328
    cudaFuncSetAttribute(mma_conv_cg2<2048, 9, 1>, cudaFuncAttributeMaxDynamicSharedMemorySize, SMEM_CG2);
    cudaFuncSetAttribute(mma_conv_cg2<512, 9, 1>,  cudaFuncAttributeMaxDynamicSharedMemorySize, SMEM_CG2);
    cudaFuncSetAttribute(mma_conv_cg2<512, 1, 0>,  cudaFuncAttributeMaxDynamicSharedMemorySize, SMEM_CG2);
    cudaFuncSetAttribute(mma_proj_cg1<512>,        cudaFuncAttributeMaxDynamicSharedMemorySize, SMEM_P1);

    // launch order keeps conv1 at index 2 so ncu's capture window samples it
    prep_wconv<<<(512 * 2048 + 255) / 256, 256>>>(c1w, w1hi, w1lo, 512, 2048);   // 0
    prep_act<<<dim3(128, 64, 4), dim3(32, 8)>>>(x, xh, 2048);                    // 1
    mma_conv_cg2<2048, 9, 1><<<dim3(4, 32), 256, SMEM_CG2>>>(                    // 2: conv1
        w1hi, w1lo, xh, bn1g, bn1b, bn1m, bn1v, fA, 512);
    prep_wqk<<<256, 256>>>(qw, kw, qb, kb, wqkhi, wqklo, gbqk);                  // 3
    prep_wlin<<<(512 * 512 + 255) / 256, 256>>>(vw, wvhi, wvlo, 512 * 512);      // 4
    prep_wconv<<<(512 * 512 + 255) / 256, 256>>>(c2w, w2hi, w2lo, 512, 512);     // 5

    // --- 2x criss-cross attention ---
    float* cur = fA;
    float* nxt = fB;
    for (int it = 0; it < 2; ++it) {
        prep_act<<<dim3(128, 16, 4), dim3(32, 8)>>>(cur, fh, 512);
        mma_proj_cg1<512><<<dim3(1, 128), 256, SMEM_P1>>>(
            wqkhi, wqklo, fh, gbqk, gqk, 128);
        mma_conv_cg2<512, 1, 0><<<dim3(4, 32), 256, SMEM_CG2>>>(
            wvhi, wvlo, fh, vb, nullptr, nullptr, nullptr, gv, 512);
        energyH_kernel<<<dim3(64, 4), 256>>>(gqk, gat);
        energyW_kernel<<<dim3(64, 4), 256>>>(gqk, gat);
        softmax_kernel<<<NPIX_ / 8, 256>>>(gat);
        aggH_kernel<<<dim3(64, 4, 8), 256>>>(gv, gat, cur, nxt, gamma);
        aggW_kernel<<<dim3(64, 4, 8), 256>>>(gv, gat, nxt, gamma);
        float* tmp = cur; cur = nxt; nxt = tmp;
    }

    // --- conv2 + BN + ReLU ---
    prep_act<<<dim3(128, 16, 4), dim3(32, 8)>>>(cur, fh, 512);
    mma_conv_cg2<512, 9, 1><<<dim3(4, 32), 256, SMEM_CG2>>>(
        w2hi, w2lo, fh, bn2g, bn2b, bn2m, bn2v, out, 512);
}